// round 1
// baseline (speedup 1.0000x reference)
#include <cuda_runtime.h>
#include <cstdint>

// Problem constants
#define DMODEL 768
#define NHEADS 12
#define DKH    64
#define NB     2
#define SEQ    4096
#define MTOT   (NB * SEQ)   // 8192

// Scratch (device globals: allocation-free contract)
__device__ float g_q[NB * NHEADS * SEQ * DKH];
__device__ float g_k[NB * NHEADS * SEQ * DKH];
__device__ float g_v[NB * NHEADS * SEQ * DKH];
__device__ float g_ctx[MTOT * DMODEL];

__device__ __forceinline__ uint32_t f2tf(float x) {
    uint32_t u;
    asm("cvt.rna.tf32.f32 %0, %1;" : "=r"(u) : "f"(x));
    return u;
}

__device__ __forceinline__ void mma8(float* c, const uint32_t* a, uint32_t b0, uint32_t b1) {
    asm volatile(
        "mma.sync.aligned.m16n8k8.row.col.f32.tf32.tf32.f32 "
        "{%0,%1,%2,%3}, {%4,%5,%6,%7}, {%8,%9}, {%0,%1,%2,%3};"
        : "+f"(c[0]), "+f"(c[1]), "+f"(c[2]), "+f"(c[3])
        : "r"(a[0]), "r"(a[1]), "r"(a[2]), "r"(a[3]), "r"(b0), "r"(b1));
}

// ---------------------------------------------------------------------------
// GEMM: Y[m,n] = sum_k X[m,k] * W[k,n] + bias[n]
// MODE 0: X = input x; W/bias chosen by blockIdx.z (wq/wk/wv); output scattered
//         into g_q/g_k/g_v with layout [B,H,S,dk].
// MODE 1: X = g_ctx; W = wo; plain row-major output into OutP.
// Tile: BM=128, BN=64, BK=32, 256 threads (8 warps: 4 x 2 of 32x32 warp tiles)
// ---------------------------------------------------------------------------
template <int MODE>
__global__ __launch_bounds__(256) void gemm_kernel(
    const float* __restrict__ Xin,
    const float* __restrict__ W0, const float* __restrict__ Bias0,
    const float* __restrict__ W1, const float* __restrict__ Bias1,
    const float* __restrict__ W2, const float* __restrict__ Bias2,
    float* __restrict__ OutP)
{
    __shared__ uint32_t As[128 * 36];  // 128 x 32 (+4 pad)
    __shared__ uint32_t Bs[32 * 68];   // 32 x 64 (+4 pad)

    const int tid = threadIdx.x;
    const int wid = tid >> 5, lane = tid & 31;
    const int g = lane >> 2, tg = lane & 3;
    const int wm = wid & 3, wn = wid >> 2;
    const int m0 = blockIdx.y * 128;
    const int n0 = blockIdx.x * 64;

    const float* X;
    const float* W;
    const float* Bias;
    if (MODE == 0) {
        X = Xin;
        const int z = blockIdx.z;
        W    = (z == 0) ? W0 : (z == 1) ? W1 : W2;
        Bias = (z == 0) ? Bias0 : (z == 1) ? Bias1 : Bias2;
    } else {
        X = g_ctx;
        W = W0;
        Bias = Bias0;
    }

    float4 aR[4], bR[2];

    // prefetch k-tile 0
    {
        const float* src = X + (size_t)m0 * DMODEL;
#pragma unroll
        for (int i = 0; i < 4; i++) {
            int lin = tid + i * 256;
            aR[i] = *(const float4*)(src + (size_t)(lin >> 3) * DMODEL + (lin & 7) * 4);
        }
        const float* wsrc = W + n0;
#pragma unroll
        for (int i = 0; i < 2; i++) {
            int lin = tid + i * 256;
            bR[i] = *(const float4*)(wsrc + (size_t)(lin >> 4) * DMODEL + (lin & 15) * 4);
        }
    }

    float acc[2][4][4];
#pragma unroll
    for (int mt = 0; mt < 2; mt++)
#pragma unroll
        for (int nt = 0; nt < 4; nt++)
#pragma unroll
            for (int i = 0; i < 4; i++) acc[mt][nt][i] = 0.f;

    const int NKT = DMODEL / 32;  // 24
    for (int kt = 0; kt < NKT; kt++) {
        __syncthreads();
#pragma unroll
        for (int i = 0; i < 4; i++) {
            int lin = tid + i * 256;
            int r = lin >> 3, c = (lin & 7) * 4;
            As[r * 36 + c + 0] = f2tf(aR[i].x);
            As[r * 36 + c + 1] = f2tf(aR[i].y);
            As[r * 36 + c + 2] = f2tf(aR[i].z);
            As[r * 36 + c + 3] = f2tf(aR[i].w);
        }
#pragma unroll
        for (int i = 0; i < 2; i++) {
            int lin = tid + i * 256;
            int r = lin >> 4, c = (lin & 15) * 4;
            Bs[r * 68 + c + 0] = f2tf(bR[i].x);
            Bs[r * 68 + c + 1] = f2tf(bR[i].y);
            Bs[r * 68 + c + 2] = f2tf(bR[i].z);
            Bs[r * 68 + c + 3] = f2tf(bR[i].w);
        }
        __syncthreads();

        if (kt + 1 < NKT) {
            const float* src = X + (size_t)m0 * DMODEL + (kt + 1) * 32;
#pragma unroll
            for (int i = 0; i < 4; i++) {
                int lin = tid + i * 256;
                aR[i] = *(const float4*)(src + (size_t)(lin >> 3) * DMODEL + (lin & 7) * 4);
            }
            const float* wsrc = W + (size_t)(kt + 1) * 32 * DMODEL + n0;
#pragma unroll
            for (int i = 0; i < 2; i++) {
                int lin = tid + i * 256;
                bR[i] = *(const float4*)(wsrc + (size_t)(lin >> 4) * DMODEL + (lin & 15) * 4);
            }
        }

#pragma unroll
        for (int ks = 0; ks < 4; ks++) {
            uint32_t a[2][4];
#pragma unroll
            for (int mt = 0; mt < 2; mt++) {
                int r = wm * 32 + mt * 16;
                a[mt][0] = As[(r + g) * 36 + ks * 8 + tg];
                a[mt][1] = As[(r + 8 + g) * 36 + ks * 8 + tg];
                a[mt][2] = As[(r + g) * 36 + ks * 8 + tg + 4];
                a[mt][3] = As[(r + 8 + g) * 36 + ks * 8 + tg + 4];
            }
#pragma unroll
            for (int nt = 0; nt < 4; nt++) {
                uint32_t b0 = Bs[(ks * 8 + tg) * 68 + wn * 32 + nt * 8 + g];
                uint32_t b1 = Bs[(ks * 8 + tg + 4) * 68 + wn * 32 + nt * 8 + g];
                mma8(acc[0][nt], a[0], b0, b1);
                mma8(acc[1][nt], a[1], b0, b1);
            }
        }
    }

    // epilogue
#pragma unroll
    for (int mt = 0; mt < 2; mt++) {
#pragma unroll
        for (int nt = 0; nt < 4; nt++) {
            int row = m0 + wm * 32 + mt * 16 + g;
            int col = n0 + wn * 32 + nt * 8 + 2 * tg;
            float bv0 = Bias[col], bv1 = Bias[col + 1];
            float2 v0 = make_float2(acc[mt][nt][0] + bv0, acc[mt][nt][1] + bv1);
            float2 v1 = make_float2(acc[mt][nt][2] + bv0, acc[mt][nt][3] + bv1);
            if (MODE == 0) {
                float* dst = (blockIdx.z == 0) ? g_q : (blockIdx.z == 1) ? g_k : g_v;
                int bb = row >> 12, s = row & 4095;
                int h = col >> 6, d = col & 63;
                size_t base0 = (((size_t)(bb * NHEADS + h)) * SEQ + s) * DKH + d;
                size_t base1 = (((size_t)(bb * NHEADS + h)) * SEQ + (s + 8)) * DKH + d;
                *(float2*)&dst[base0] = v0;
                *(float2*)&dst[base1] = v1;
            } else {
                *(float2*)&OutP[(size_t)row * DMODEL + col] = v0;
                *(float2*)&OutP[(size_t)(row + 8) * DMODEL + col] = v1;
            }
        }
    }
}

// ---------------------------------------------------------------------------
// Flash attention: CTA = (128 q rows, one (b,h)); 8 warps x 16 q-rows each.
// K/V tiles of 64 keys in smem (tf32 bits); online softmax; P staged through
// warp-private smem rows for the C->A fragment relayout.
// ---------------------------------------------------------------------------
#define ATTN_SMEM_BYTES ((128 * 68 + 64 * 68 + 64 * 68) * 4)

__global__ __launch_bounds__(256) void attn_kernel() {
    extern __shared__ uint32_t sm[];
    uint32_t* Ps = sm;                 // 128 x 68 (Q staging, then P staging)
    uint32_t* Ks = sm + 128 * 68;      // 64 x 68
    uint32_t* Vs = Ks + 64 * 68;       // 64 x 68

    const int tid = threadIdx.x;
    const int wid = tid >> 5, lane = tid & 31;
    const int g = lane >> 2, tg = lane & 3;
    const int wb = wid * 16;
    const int bh = blockIdx.y;        // b*NHEADS + h
    const int q0 = blockIdx.x * 128;

    const float* Qg = g_q + (size_t)bh * SEQ * DKH;
    const float* Kg = g_k + (size_t)bh * SEQ * DKH;
    const float* Vg = g_v + (size_t)bh * SEQ * DKH;

    // stage Q tile (128 x 64) -> Ps as tf32
#pragma unroll
    for (int i = 0; i < 8; i++) {
        int lin = tid + i * 256;
        int r = lin >> 4, c = (lin & 15) * 4;
        float4 v = *(const float4*)(Qg + (size_t)(q0 + r) * DKH + c);
        Ps[r * 68 + c + 0] = f2tf(v.x);
        Ps[r * 68 + c + 1] = f2tf(v.y);
        Ps[r * 68 + c + 2] = f2tf(v.z);
        Ps[r * 68 + c + 3] = f2tf(v.w);
    }
    __syncthreads();

    // Q A-fragments, register resident for the whole kernel
    uint32_t qa[8][4];
#pragma unroll
    for (int ks = 0; ks < 8; ks++) {
        qa[ks][0] = Ps[(wb + g) * 68 + ks * 8 + tg];
        qa[ks][1] = Ps[(wb + 8 + g) * 68 + ks * 8 + tg];
        qa[ks][2] = Ps[(wb + g) * 68 + ks * 8 + tg + 4];
        qa[ks][3] = Ps[(wb + 8 + g) * 68 + ks * 8 + tg + 4];
    }

    float o[8][4];
#pragma unroll
    for (int nt = 0; nt < 8; nt++)
#pragma unroll
        for (int i = 0; i < 4; i++) o[nt][i] = 0.f;
    float m0v = -1e30f, m1v = -1e30f, l0 = 0.f, l1 = 0.f;

    for (int kt = 0; kt < SEQ / 64; kt++) {
        __syncthreads();  // protect Ks/Vs (and Ps across warps via program order)
        // load K and V tiles (64 x 64 each) -> smem as tf32
#pragma unroll
        for (int i = 0; i < 4; i++) {
            int lin = tid + i * 256;
            int r = lin >> 4, c = (lin & 15) * 4;
            float4 kv = *(const float4*)(Kg + (size_t)(kt * 64 + r) * DKH + c);
            Ks[r * 68 + c + 0] = f2tf(kv.x);
            Ks[r * 68 + c + 1] = f2tf(kv.y);
            Ks[r * 68 + c + 2] = f2tf(kv.z);
            Ks[r * 68 + c + 3] = f2tf(kv.w);
            float4 vv = *(const float4*)(Vg + (size_t)(kt * 64 + r) * DKH + c);
            Vs[r * 68 + c + 0] = f2tf(vv.x);
            Vs[r * 68 + c + 1] = f2tf(vv.y);
            Vs[r * 68 + c + 2] = f2tf(vv.z);
            Vs[r * 68 + c + 3] = f2tf(vv.w);
        }
        __syncthreads();

        // scores: S = Q K^T  (16 x 64 per warp)
        float sc[8][4];
#pragma unroll
        for (int nt = 0; nt < 8; nt++)
#pragma unroll
            for (int i = 0; i < 4; i++) sc[nt][i] = 0.f;
#pragma unroll
        for (int nt = 0; nt < 8; nt++) {
#pragma unroll
            for (int ks = 0; ks < 8; ks++) {
                uint32_t b0 = Ks[(nt * 8 + g) * 68 + ks * 8 + tg];
                uint32_t b1 = Ks[(nt * 8 + g) * 68 + ks * 8 + tg + 4];
                mma8(sc[nt], qa[ks], b0, b1);
            }
        }

        // online softmax (rows g and g+8 of this warp's stripe)
        float mx0 = -1e30f, mx1 = -1e30f;
#pragma unroll
        for (int nt = 0; nt < 8; nt++) {
            sc[nt][0] *= 0.125f;
            sc[nt][1] *= 0.125f;
            sc[nt][2] *= 0.125f;
            sc[nt][3] *= 0.125f;
            mx0 = fmaxf(mx0, fmaxf(sc[nt][0], sc[nt][1]));
            mx1 = fmaxf(mx1, fmaxf(sc[nt][2], sc[nt][3]));
        }
        mx0 = fmaxf(mx0, __shfl_xor_sync(0xffffffffu, mx0, 1));
        mx0 = fmaxf(mx0, __shfl_xor_sync(0xffffffffu, mx0, 2));
        mx1 = fmaxf(mx1, __shfl_xor_sync(0xffffffffu, mx1, 1));
        mx1 = fmaxf(mx1, __shfl_xor_sync(0xffffffffu, mx1, 2));
        float mn0 = fmaxf(m0v, mx0), mn1 = fmaxf(m1v, mx1);
        float al0 = __expf(m0v - mn0), al1 = __expf(m1v - mn1);
        m0v = mn0;
        m1v = mn1;

        float rs0 = 0.f, rs1 = 0.f;
#pragma unroll
        for (int nt = 0; nt < 8; nt++) {
            float p00 = __expf(sc[nt][0] - mn0);
            float p01 = __expf(sc[nt][1] - mn0);
            float p10 = __expf(sc[nt][2] - mn1);
            float p11 = __expf(sc[nt][3] - mn1);
            rs0 += p00 + p01;
            rs1 += p10 + p11;
            int c = nt * 8 + 2 * tg;
            Ps[(wb + g) * 68 + c] = f2tf(p00);
            Ps[(wb + g) * 68 + c + 1] = f2tf(p01);
            Ps[(wb + 8 + g) * 68 + c] = f2tf(p10);
            Ps[(wb + 8 + g) * 68 + c + 1] = f2tf(p11);
        }
        rs0 += __shfl_xor_sync(0xffffffffu, rs0, 1);
        rs0 += __shfl_xor_sync(0xffffffffu, rs0, 2);
        rs1 += __shfl_xor_sync(0xffffffffu, rs1, 1);
        rs1 += __shfl_xor_sync(0xffffffffu, rs1, 2);
        l0 = l0 * al0 + rs0;
        l1 = l1 * al1 + rs1;

#pragma unroll
        for (int nt = 0; nt < 8; nt++) {
            o[nt][0] *= al0;
            o[nt][1] *= al0;
            o[nt][2] *= al1;
            o[nt][3] *= al1;
        }
        __syncwarp();  // P writes -> P reads (warp-private rows)

        // O += P V
#pragma unroll
        for (int ks = 0; ks < 8; ks++) {
            uint32_t pa[4];
            pa[0] = Ps[(wb + g) * 68 + ks * 8 + tg];
            pa[1] = Ps[(wb + 8 + g) * 68 + ks * 8 + tg];
            pa[2] = Ps[(wb + g) * 68 + ks * 8 + tg + 4];
            pa[3] = Ps[(wb + 8 + g) * 68 + ks * 8 + tg + 4];
#pragma unroll
            for (int nt = 0; nt < 8; nt++) {
                uint32_t b0 = Vs[(ks * 8 + tg) * 68 + nt * 8 + g];
                uint32_t b1 = Vs[(ks * 8 + tg + 4) * 68 + nt * 8 + g];
                mma8(o[nt], pa, b0, b1);
            }
        }
    }

    // finalize and write context in [B,S,D] layout (col = h*64 + d)
    const int bb = bh / NHEADS, h = bh % NHEADS;
    const float inv0 = 1.f / l0, inv1 = 1.f / l1;
    const int s0 = q0 + wb + g;
#pragma unroll
    for (int nt = 0; nt < 8; nt++) {
        int col = h * DKH + nt * 8 + 2 * tg;
        *(float2*)&g_ctx[((size_t)(bb * SEQ + s0)) * DMODEL + col] =
            make_float2(o[nt][0] * inv0, o[nt][1] * inv0);
        *(float2*)&g_ctx[((size_t)(bb * SEQ + s0 + 8)) * DMODEL + col] =
            make_float2(o[nt][2] * inv1, o[nt][3] * inv1);
    }
}

// ---------------------------------------------------------------------------
extern "C" void kernel_launch(void* const* d_in, const int* in_sizes, int n_in,
                              void* d_out, int out_size) {
    const float* x  = (const float*)d_in[0];
    const float* wq = (const float*)d_in[1];
    const float* bq = (const float*)d_in[2];
    const float* wk = (const float*)d_in[3];
    const float* bk = (const float*)d_in[4];
    const float* wv = (const float*)d_in[5];
    const float* bv = (const float*)d_in[6];
    const float* wo = (const float*)d_in[7];
    const float* bo = (const float*)d_in[8];
    float* out = (float*)d_out;

    dim3 blk(256);

    // 1) fused QKV projection (z selects wq/wk/wv), scatter into [B,H,S,dk]
    gemm_kernel<0><<<dim3(DMODEL / 64, MTOT / 128, 3), blk>>>(
        x, wq, bq, wk, bk, wv, bv, nullptr);

    // 2) flash attention -> g_ctx [B,S,D]
    cudaFuncSetAttribute(attn_kernel, cudaFuncAttributeMaxDynamicSharedMemorySize,
                         ATTN_SMEM_BYTES);
    attn_kernel<<<dim3(SEQ / 128, NB * NHEADS), blk, ATTN_SMEM_BYTES>>>();

    // 3) output projection -> d_out
    gemm_kernel<1><<<dim3(DMODEL / 64, MTOT / 128, 1), blk>>>(
        nullptr, wo, bo, nullptr, nullptr, nullptr, nullptr, out);
}

// round 2
// speedup vs baseline: 1.3777x; 1.3777x over previous
#include <cuda_runtime.h>
#include <cstdint>

// Problem constants
#define DMODEL 768
#define NHEADS 12
#define DKH    64
#define NB     2
#define SEQ    4096
#define MTOT   (NB * SEQ)   // 8192

// Scratch (device globals: allocation-free contract)
__device__ float g_q[NB * NHEADS * SEQ * DKH];
__device__ float g_k[NB * NHEADS * SEQ * DKH];
__device__ float g_v[NB * NHEADS * SEQ * DKH];
__device__ float g_ctx[MTOT * DMODEL];

__device__ __forceinline__ uint32_t f2tf(float x) {
    uint32_t u;
    asm("cvt.rna.tf32.f32 %0, %1;" : "=r"(u) : "f"(x));
    return u;
}

__device__ __forceinline__ void mma8(float* c, const uint32_t* a, uint32_t b0, uint32_t b1) {
    asm volatile(
        "mma.sync.aligned.m16n8k8.row.col.f32.tf32.tf32.f32 "
        "{%0,%1,%2,%3}, {%4,%5,%6,%7}, {%8,%9}, {%0,%1,%2,%3};"
        : "+f"(c[0]), "+f"(c[1]), "+f"(c[2]), "+f"(c[3])
        : "r"(a[0]), "r"(a[1]), "r"(a[2]), "r"(a[3]), "r"(b0), "r"(b1));
}

__device__ __forceinline__ void cp16(void* dst, const void* src) {
    uint32_t d = (uint32_t)__cvta_generic_to_shared(dst);
    asm volatile("cp.async.cg.shared.global [%0], [%1], 16;" :: "r"(d), "l"(src));
}
__device__ __forceinline__ void cp_commit() { asm volatile("cp.async.commit_group;"); }
template <int N>
__device__ __forceinline__ void cp_wait() { asm volatile("cp.async.wait_group %0;" :: "n"(N)); }

// ---------------------------------------------------------------------------
// GEMM: Y[m,n] = sum_k X[m,k] * W[k,n] + bias[n]
// cp.async double-buffered; raw fp32 in smem; tf32 cvt at fragment load.
// Tile: BM=128, BN=64, BK=32, 256 threads (8 warps, 4m x 2n of 32x32).
// ---------------------------------------------------------------------------
#define GEMM_SMEM ((2 * 128 * 36 + 2 * 32 * 68) * 4)

template <int MODE>
__global__ __launch_bounds__(256) void gemm_kernel(
    const float* __restrict__ Xin,
    const float* __restrict__ W0, const float* __restrict__ Bias0,
    const float* __restrict__ W1, const float* __restrict__ Bias1,
    const float* __restrict__ W2, const float* __restrict__ Bias2,
    float* __restrict__ OutP)
{
    extern __shared__ float gsm[];
    float* As = gsm;               // 2 x 128 x 36
    float* Bs = gsm + 2 * 128 * 36;  // 2 x 32 x 68

    const int tid = threadIdx.x;
    const int wid = tid >> 5, lane = tid & 31;
    const int g = lane >> 2, tg = lane & 3;
    const int wm = wid & 3, wn = wid >> 2;
    const int m0 = blockIdx.y * 128;
    const int n0 = blockIdx.x * 64;

    const float* X;
    const float* W;
    const float* Bias;
    if (MODE == 0) {
        X = Xin;
        const int z = blockIdx.z;
        W    = (z == 0) ? W0 : (z == 1) ? W1 : W2;
        Bias = (z == 0) ? Bias0 : (z == 1) ? Bias1 : Bias2;
    } else {
        X = g_ctx;
        W = W0;
        Bias = Bias0;
    }

    // issue k-tile kt into buffer buf
    auto load_tile = [&](int kt, int buf) {
        const float* src = X + (size_t)m0 * DMODEL + kt * 32;
        float* Ad = As + buf * 128 * 36;
#pragma unroll
        for (int i = 0; i < 4; i++) {
            int lin = tid + i * 256;
            int r = lin >> 3, c = (lin & 7) * 4;
            cp16(&Ad[r * 36 + c], src + (size_t)r * DMODEL + c);
        }
        const float* wsrc = W + (size_t)kt * 32 * DMODEL + n0;
        float* Bd = Bs + buf * 32 * 68;
#pragma unroll
        for (int i = 0; i < 2; i++) {
            int lin = tid + i * 256;
            int r = lin >> 4, c = (lin & 15) * 4;
            cp16(&Bd[r * 68 + c], wsrc + (size_t)r * DMODEL + c);
        }
        cp_commit();
    };

    float acc[2][4][4];
#pragma unroll
    for (int mt = 0; mt < 2; mt++)
#pragma unroll
        for (int nt = 0; nt < 4; nt++)
#pragma unroll
            for (int i = 0; i < 4; i++) acc[mt][nt][i] = 0.f;

    const int NKT = DMODEL / 32;  // 24
    load_tile(0, 0);

    for (int kt = 0; kt < NKT; kt++) {
        if (kt + 1 < NKT) {
            load_tile(kt + 1, (kt + 1) & 1);
            cp_wait<1>();
        } else {
            cp_wait<0>();
        }
        __syncthreads();

        const float* Ac = As + (kt & 1) * 128 * 36;
        const float* Bc = Bs + (kt & 1) * 32 * 68;

#pragma unroll
        for (int ks = 0; ks < 4; ks++) {
            uint32_t a[2][4];
#pragma unroll
            for (int mt = 0; mt < 2; mt++) {
                int r = wm * 32 + mt * 16;
                a[mt][0] = f2tf(Ac[(r + g) * 36 + ks * 8 + tg]);
                a[mt][1] = f2tf(Ac[(r + 8 + g) * 36 + ks * 8 + tg]);
                a[mt][2] = f2tf(Ac[(r + g) * 36 + ks * 8 + tg + 4]);
                a[mt][3] = f2tf(Ac[(r + 8 + g) * 36 + ks * 8 + tg + 4]);
            }
#pragma unroll
            for (int nt = 0; nt < 4; nt++) {
                uint32_t b0 = f2tf(Bc[(ks * 8 + tg) * 68 + wn * 32 + nt * 8 + g]);
                uint32_t b1 = f2tf(Bc[(ks * 8 + tg + 4) * 68 + wn * 32 + nt * 8 + g]);
                mma8(acc[0][nt], a[0], b0, b1);
                mma8(acc[1][nt], a[1], b0, b1);
            }
        }
        __syncthreads();
    }

    // epilogue
#pragma unroll
    for (int mt = 0; mt < 2; mt++) {
#pragma unroll
        for (int nt = 0; nt < 4; nt++) {
            int row = m0 + wm * 32 + mt * 16 + g;
            int col = n0 + wn * 32 + nt * 8 + 2 * tg;
            float bv0 = Bias[col], bv1 = Bias[col + 1];
            float2 v0 = make_float2(acc[mt][nt][0] + bv0, acc[mt][nt][1] + bv1);
            float2 v1 = make_float2(acc[mt][nt][2] + bv0, acc[mt][nt][3] + bv1);
            if (MODE == 0) {
                float* dst = (blockIdx.z == 0) ? g_q : (blockIdx.z == 1) ? g_k : g_v;
                int bb = row >> 12, s = row & 4095;
                int h = col >> 6, d = col & 63;
                size_t base0 = (((size_t)(bb * NHEADS + h)) * SEQ + s) * DKH + d;
                size_t base1 = (((size_t)(bb * NHEADS + h)) * SEQ + (s + 8)) * DKH + d;
                *(float2*)&dst[base0] = v0;
                *(float2*)&dst[base1] = v1;
            } else {
                *(float2*)&OutP[(size_t)row * DMODEL + col] = v0;
                *(float2*)&OutP[(size_t)(row + 8) * DMODEL + col] = v1;
            }
        }
    }
}

// ---------------------------------------------------------------------------
// Flash attention: CTA = 256 q rows of one (b,h); 8 warps x 32 q-rows each
// (2 m-subtiles per warp -> K/V fragments reused 2x). cp.async double-buffered
// K/V tiles (raw fp32); Q fragments register-resident; online softmax; P
// staged through warp-private smem rows (tf32 bits) for the C->A relayout.
// ---------------------------------------------------------------------------
#define ATT_SMEM ((256 * 68 + 4 * 64 * 68) * 4)

__global__ __launch_bounds__(256, 1) void attn_kernel() {
    extern __shared__ float sm[];
    float* Qs = sm;                    // 256 x 68 : Q staging, then P staging
    float* Kb = sm + 256 * 68;         // 2 x 64 x 68
    float* Vb = Kb + 2 * 64 * 68;      // 2 x 64 x 68
    uint32_t* Ps = (uint32_t*)Qs;      // P staged as tf32 bit patterns

    const int tid = threadIdx.x;
    const int wid = tid >> 5, lane = tid & 31;
    const int g = lane >> 2, tg = lane & 3;
    const int wb = wid * 32;
    const int bh = blockIdx.y;
    const int q0 = blockIdx.x * 256;

    const float* Qg = g_q + (size_t)bh * SEQ * DKH;
    const float* Kg = g_k + (size_t)bh * SEQ * DKH;
    const float* Vg = g_v + (size_t)bh * SEQ * DKH;

    // stage Q tile (256 x 64, raw fp32)
#pragma unroll
    for (int i = 0; i < 16; i++) {
        int lin = tid + i * 256;
        int r = lin >> 4, c = (lin & 15) * 4;
        *(float4*)&Qs[r * 68 + c] = *(const float4*)(Qg + (size_t)(q0 + r) * DKH + c);
    }
    __syncthreads();

    // Q A-fragments (2 m-subtiles), register resident for whole kernel
    uint32_t qa[2][8][4];
#pragma unroll
    for (int mt = 0; mt < 2; mt++) {
        int r = wb + mt * 16;
#pragma unroll
        for (int ks = 0; ks < 8; ks++) {
            qa[mt][ks][0] = f2tf(Qs[(r + g) * 68 + ks * 8 + tg]);
            qa[mt][ks][1] = f2tf(Qs[(r + 8 + g) * 68 + ks * 8 + tg]);
            qa[mt][ks][2] = f2tf(Qs[(r + g) * 68 + ks * 8 + tg + 4]);
            qa[mt][ks][3] = f2tf(Qs[(r + 8 + g) * 68 + ks * 8 + tg + 4]);
        }
    }
    // (no barrier needed: each warp only reads/writes its own 32 rows of Qs/Ps)

    float o[2][8][4];
#pragma unroll
    for (int mt = 0; mt < 2; mt++)
#pragma unroll
        for (int nt = 0; nt < 8; nt++)
#pragma unroll
            for (int i = 0; i < 4; i++) o[mt][nt][i] = 0.f;
    float mrow[2][2] = {{-1e30f, -1e30f}, {-1e30f, -1e30f}};
    float lrow[2][2] = {{0.f, 0.f}, {0.f, 0.f}};

    auto load_kv = [&](int kt, int buf) {
        float* Kd = Kb + buf * 64 * 68;
        float* Vd = Vb + buf * 64 * 68;
#pragma unroll
        for (int i = 0; i < 4; i++) {
            int lin = tid + i * 256;
            int r = lin >> 4, c = (lin & 15) * 4;
            cp16(&Kd[r * 68 + c], Kg + (size_t)(kt * 64 + r) * DKH + c);
            cp16(&Vd[r * 68 + c], Vg + (size_t)(kt * 64 + r) * DKH + c);
        }
        cp_commit();
    };

    load_kv(0, 0);

    for (int kt = 0; kt < SEQ / 64; kt++) {
        if (kt + 1 < SEQ / 64) {
            load_kv(kt + 1, (kt + 1) & 1);
            cp_wait<1>();
        } else {
            cp_wait<0>();
        }
        __syncthreads();

        const float* Ks = Kb + (kt & 1) * 64 * 68;
        const float* Vs = Vb + (kt & 1) * 64 * 68;

        // scores: S = Q K^T  (32 x 64 per warp, K fragments reused across mt)
        float sc[2][8][4];
#pragma unroll
        for (int mt = 0; mt < 2; mt++)
#pragma unroll
            for (int nt = 0; nt < 8; nt++)
#pragma unroll
                for (int i = 0; i < 4; i++) sc[mt][nt][i] = 0.f;
#pragma unroll
        for (int nt = 0; nt < 8; nt++) {
#pragma unroll
            for (int ks = 0; ks < 8; ks++) {
                uint32_t b0 = f2tf(Ks[(nt * 8 + g) * 68 + ks * 8 + tg]);
                uint32_t b1 = f2tf(Ks[(nt * 8 + g) * 68 + ks * 8 + tg + 4]);
                mma8(sc[0][nt], qa[0][ks], b0, b1);
                mma8(sc[1][nt], qa[1][ks], b0, b1);
            }
        }

        // online softmax per m-subtile (rows g and g+8 of each 16-row stripe)
#pragma unroll
        for (int mt = 0; mt < 2; mt++) {
            float mx0 = -1e30f, mx1 = -1e30f;
#pragma unroll
            for (int nt = 0; nt < 8; nt++) {
                sc[mt][nt][0] *= 0.125f;
                sc[mt][nt][1] *= 0.125f;
                sc[mt][nt][2] *= 0.125f;
                sc[mt][nt][3] *= 0.125f;
                mx0 = fmaxf(mx0, fmaxf(sc[mt][nt][0], sc[mt][nt][1]));
                mx1 = fmaxf(mx1, fmaxf(sc[mt][nt][2], sc[mt][nt][3]));
            }
            mx0 = fmaxf(mx0, __shfl_xor_sync(0xffffffffu, mx0, 1));
            mx0 = fmaxf(mx0, __shfl_xor_sync(0xffffffffu, mx0, 2));
            mx1 = fmaxf(mx1, __shfl_xor_sync(0xffffffffu, mx1, 1));
            mx1 = fmaxf(mx1, __shfl_xor_sync(0xffffffffu, mx1, 2));
            float mn0 = fmaxf(mrow[mt][0], mx0), mn1 = fmaxf(mrow[mt][1], mx1);
            float al0 = __expf(mrow[mt][0] - mn0), al1 = __expf(mrow[mt][1] - mn1);
            mrow[mt][0] = mn0;
            mrow[mt][1] = mn1;

            int r = wb + mt * 16;
            float rs0 = 0.f, rs1 = 0.f;
#pragma unroll
            for (int nt = 0; nt < 8; nt++) {
                float p00 = __expf(sc[mt][nt][0] - mn0);
                float p01 = __expf(sc[mt][nt][1] - mn0);
                float p10 = __expf(sc[mt][nt][2] - mn1);
                float p11 = __expf(sc[mt][nt][3] - mn1);
                rs0 += p00 + p01;
                rs1 += p10 + p11;
                int c = nt * 8 + 2 * tg;
                Ps[(r + g) * 68 + c] = f2tf(p00);
                Ps[(r + g) * 68 + c + 1] = f2tf(p01);
                Ps[(r + 8 + g) * 68 + c] = f2tf(p10);
                Ps[(r + 8 + g) * 68 + c + 1] = f2tf(p11);
            }
            rs0 += __shfl_xor_sync(0xffffffffu, rs0, 1);
            rs0 += __shfl_xor_sync(0xffffffffu, rs0, 2);
            rs1 += __shfl_xor_sync(0xffffffffu, rs1, 1);
            rs1 += __shfl_xor_sync(0xffffffffu, rs1, 2);
            lrow[mt][0] = lrow[mt][0] * al0 + rs0;
            lrow[mt][1] = lrow[mt][1] * al1 + rs1;

#pragma unroll
            for (int nt = 0; nt < 8; nt++) {
                o[mt][nt][0] *= al0;
                o[mt][nt][1] *= al0;
                o[mt][nt][2] *= al1;
                o[mt][nt][3] *= al1;
            }
        }
        __syncwarp();  // P writes -> P reads (warp-private rows)

        // O += P V  (V fragments reused across mt)
#pragma unroll
        for (int ks = 0; ks < 8; ks++) {
            uint32_t pa[2][4];
#pragma unroll
            for (int mt = 0; mt < 2; mt++) {
                int r = wb + mt * 16;
                pa[mt][0] = Ps[(r + g) * 68 + ks * 8 + tg];
                pa[mt][1] = Ps[(r + 8 + g) * 68 + ks * 8 + tg];
                pa[mt][2] = Ps[(r + g) * 68 + ks * 8 + tg + 4];
                pa[mt][3] = Ps[(r + 8 + g) * 68 + ks * 8 + tg + 4];
            }
#pragma unroll
            for (int nt = 0; nt < 8; nt++) {
                uint32_t b0 = f2tf(Vs[(ks * 8 + tg) * 68 + nt * 8 + g]);
                uint32_t b1 = f2tf(Vs[(ks * 8 + tg + 4) * 68 + nt * 8 + g]);
                mma8(o[0][nt], pa[0], b0, b1);
                mma8(o[1][nt], pa[1], b0, b1);
            }
        }
        __syncthreads();  // compute done before next iter overwrites this buffer
    }

    // finalize and write context in [B,S,D] layout (col = h*64 + d)
    const int bb = bh / NHEADS, h = bh % NHEADS;
#pragma unroll
    for (int mt = 0; mt < 2; mt++) {
        const float inv0 = 1.f / lrow[mt][0], inv1 = 1.f / lrow[mt][1];
        const int s0 = q0 + wb + mt * 16 + g;
#pragma unroll
        for (int nt = 0; nt < 8; nt++) {
            int col = h * DKH + nt * 8 + 2 * tg;
            *(float2*)&g_ctx[((size_t)(bb * SEQ + s0)) * DMODEL + col] =
                make_float2(o[mt][nt][0] * inv0, o[mt][nt][1] * inv0);
            *(float2*)&g_ctx[((size_t)(bb * SEQ + s0 + 8)) * DMODEL + col] =
                make_float2(o[mt][nt][2] * inv1, o[mt][nt][3] * inv1);
        }
    }
}

// ---------------------------------------------------------------------------
extern "C" void kernel_launch(void* const* d_in, const int* in_sizes, int n_in,
                              void* d_out, int out_size) {
    const float* x  = (const float*)d_in[0];
    const float* wq = (const float*)d_in[1];
    const float* bq = (const float*)d_in[2];
    const float* wk = (const float*)d_in[3];
    const float* bk = (const float*)d_in[4];
    const float* wv = (const float*)d_in[5];
    const float* bv = (const float*)d_in[6];
    const float* wo = (const float*)d_in[7];
    const float* bo = (const float*)d_in[8];
    float* out = (float*)d_out;

    static bool attr_done = false;
    if (!attr_done) {
        cudaFuncSetAttribute(gemm_kernel<0>, cudaFuncAttributeMaxDynamicSharedMemorySize, GEMM_SMEM);
        cudaFuncSetAttribute(gemm_kernel<1>, cudaFuncAttributeMaxDynamicSharedMemorySize, GEMM_SMEM);
        cudaFuncSetAttribute(attn_kernel, cudaFuncAttributeMaxDynamicSharedMemorySize, ATT_SMEM);
        attr_done = true;
    }

    dim3 blk(256);

    // 1) fused QKV projection (z selects wq/wk/wv), scatter into [B,H,S,dk]
    gemm_kernel<0><<<dim3(DMODEL / 64, MTOT / 128, 3), blk, GEMM_SMEM>>>(
        x, wq, bq, wk, bk, wv, bv, nullptr);

    // 2) flash attention -> g_ctx [B,S,D]
    attn_kernel<<<dim3(SEQ / 256, NB * NHEADS), blk, ATT_SMEM>>>();

    // 3) output projection -> d_out
    gemm_kernel<1><<<dim3(DMODEL / 64, MTOT / 128, 1), blk, GEMM_SMEM>>>(
        nullptr, wo, bo, nullptr, nullptr, nullptr, nullptr, out);
}